// round 16
// baseline (speedup 1.0000x reference)
#include <cuda_runtime.h>
#include <cuda_fp16.h>
#include <cstdint>
#include <math.h>

// ---------------------------------------------------------------------------
// VGG16-block3 features on outputs+styles [4,3,256,256], then
// loss = mean_{b,n} (1 - max_m xn[b,n].sn[b,m]),  C=768, N=M=4096.
//
// Full fp16 datapath (fp32 accumulate) on m16n8k16 MMA, cp.async-pipelined,
// fragment loads via ldmatrix (LDSM). Structure = round-15 proven base.
// This round: specialized tap-packed layer-1 conv (K=36: 3 MMAs vs 9; input
// stored as 2 channel-pairs instead of 8 mostly-zero planes).
// Activations: zero-padded channel-pair half2 layout [C/2][H+2][W+4]; storage
// pair P=(chunk c, p) holds logical channels (16c+p, 16c+8+p). Weights
// permuted to match. Padded borders rely on .bss zero-init, never written.
// ---------------------------------------------------------------------------

#define BATCH 4
#define FEATC 768
#define FEATN 4096

__device__ __half2 g_pad0[(size_t)BATCH * 2 * 258 * 260];   // layer-1 input: 2 pairs
__device__ __half2 g_pad1[(size_t)BATCH * 32 * 258 * 260];
__device__ __half2 g_pad2[(size_t)BATCH * 32 * 258 * 260];
__device__ __half2 g_pad3[(size_t)BATCH * 32 * 130 * 132];
__device__ __half2 g_pad4[(size_t)BATCH * 64 * 130 * 132];
__device__ __half2 g_pad5[(size_t)BATCH * 64 * 130 * 132];
__device__ __half2 g_pad6[(size_t)BATCH * 64 * 66 * 68];
__device__ __half2 g_f1[(size_t)BATCH * 128 * 66 * 68];
__device__ __half2 g_f2[(size_t)BATCH * 128 * 66 * 68];
__device__ __half2 g_f3[(size_t)BATCH * 128 * 66 * 68];
__device__ __half  g_xT[(size_t)BATCH * FEATN * FEATC];
__device__ __half  g_sT[(size_t)BATCH * FEATN * FEATC];
__device__ __half2 g_wH[870912];
__device__ float   g_maxsim[BATCH * FEATN];

#define MMA_F16(c, a, bfr) \
    asm volatile("mma.sync.aligned.m16n8k16.row.col.f32.f16.f16.f32 " \
        "{%0,%1,%2,%3}, {%4,%5,%6,%7}, {%8,%9}, {%0,%1,%2,%3};" \
        : "+f"((c)[0]), "+f"((c)[1]), "+f"((c)[2]), "+f"((c)[3]) \
        : "r"((a)[0]), "r"((a)[1]), "r"((a)[2]), "r"((a)[3]), \
          "r"((bfr)[0]), "r"((bfr)[1]))

#define LDSM_X4(r0, r1, r2, r3, addr) \
    asm volatile("ldmatrix.sync.aligned.m8n8.x4.shared.b16 {%0,%1,%2,%3}, [%4];" \
        : "=r"(r0), "=r"(r1), "=r"(r2), "=r"(r3) : "r"(addr))
#define LDSM_X2(r0, r1, addr) \
    asm volatile("ldmatrix.sync.aligned.m8n8.x2.shared.b16 {%0,%1}, [%2];" \
        : "=r"(r0), "=r"(r1) : "r"(addr))

__device__ __forceinline__ void cpa16(uint32_t dst, const void* src) {
    asm volatile("cp.async.cg.shared.global [%0], [%1], 16;" :: "r"(dst), "l"(src));
}
#define CPA_COMMIT() asm volatile("cp.async.commit_group;" ::: "memory")
#define CPA_WAIT1()  asm volatile("cp.async.wait_group 1;" ::: "memory")
#define CPA_WAIT0()  asm volatile("cp.async.wait_group 0;" ::: "memory")

// ---------------------------------------------------------------------------
// input normalization -> layer-1 pair layout: pair0=(ch0,ch1), pair1=(ch2,0)
// ---------------------------------------------------------------------------
__global__ void norm_input_pad_kernel(const float* __restrict__ in, __half2* __restrict__ out) {
    int i = blockIdx.x * blockDim.x + threadIdx.x;
    if (i >= BATCH * 65536) return;
    int x = i & 255, y = (i >> 8) & 255;
    int b = i >> 16;
    const float mean[3] = {0.485f, 0.456f, 0.406f};
    const float stdv[3] = {0.229f, 0.224f, 0.225f};
    const float* src = in + ((size_t)b * 3 << 16) + (y << 8) + x;
    float v0 = (src[0] - mean[0]) / stdv[0];
    float v1 = (src[65536] - mean[1]) / stdv[1];
    float v2 = (src[131072] - mean[2]) / stdv[2];
    size_t o = ((size_t)(b * 2) * 258 + 1 + y) * 260 + 1 + x;
    out[o] = __floats2half2_rn(v0, v1);
    out[o + (size_t)258 * 260] = __floats2half2_rn(v2, 0.f);
}

// ---------------------------------------------------------------------------
// fused weight transform (single launch):
// segment 0 (i<1536): layer-1 tap-packed wL1[oc][24]: j=tap*2+p ->
//   half2 = (w0[oc][2p][tap], w0[oc][2p+1][tap]), zero for j>=18 / ch>=3.
// segments 1..6: generic wH[seg + (c*OC+oc)*72 + t*8 + p].
// ---------------------------------------------------------------------------
__global__ void wtrans_all_kernel(const float* __restrict__ w0, const float* __restrict__ w1,
                                  const float* __restrict__ w2, const float* __restrict__ w3,
                                  const float* __restrict__ w4, const float* __restrict__ w5,
                                  const float* __restrict__ w6, __half2* __restrict__ wH) {
    const int i = blockIdx.x * blockDim.x + threadIdx.x;
    if (i >= 870912) return;
    if (i < 4608) {
        float v0 = 0.f, v1 = 0.f;
        if (i < 1536) {
            int oc = i / 24, j = i % 24;
            if (j < 18) {
                int tap = j >> 1, p = j & 1;
                v0 = w0[oc * 27 + (2 * p) * 9 + tap];
                if (2 * p + 1 < 3) v1 = w0[oc * 27 + (2 * p + 1) * 9 + tap];
            }
        }
        wH[i] = __floats2half2_rn(v0, v1);
        return;
    }
    const int ends[7] = {4608, 23040, 59904, 133632, 281088, 576000, 870912};
    const int OCt[7] = {64, 64, 128, 128, 256, 256, 256};
    const int Cint[7] = {3, 64, 64, 128, 128, 256, 256};
    int L = 1;
    while (i >= ends[L]) L++;
    int base = ends[L - 1];
    const float* wsrc[7] = {w0, w1, w2, w3, w4, w5, w6};
    const float* w = wsrc[L];
    int OC = OCt[L], Cin = Cint[L];
    int j = i - base;
    int within = j % 72;
    int t = within >> 3, p = within & 7;
    int oc = (j / 72) % OC;
    int c = j / (72 * OC);
    int ic0 = 16 * c + p, ic1 = ic0 + 8;
    float v0 = (ic0 < Cin) ? w[((size_t)oc * Cin + ic0) * 9 + t] : 0.f;
    float v1 = (ic1 < Cin) ? w[((size_t)oc * Cin + ic1) * 9 + t] : 0.f;
    wH[i] = __floats2half2_rn(v0, v1);
}

// ---------------------------------------------------------------------------
// specialized layer-1 conv: 3->64, tap-packed K=36 (18 pairs), 3 MMAs.
// Block 256 thr: 64 oc x 256 px (1 row). Warps 2(oc) x 4(px).
// ---------------------------------------------------------------------------
#define L1_PW2 260
#define L1_ICS2 808         // 3*260=780 -> pad to ≡8 mod 32, mult of 4
#define L1_WST 28           // A row stride (24 pairs padded; 8 rows distinct banks)
#define L1_WS (64 * L1_WST) // 1792
#define L1_PATCH (2 * L1_ICS2)
#define L1_ZOFF L1_PATCH    // zero region start (in patch half2 units)

__global__ __launch_bounds__(256, 2)
void conv1_mma_f16(const __half2* __restrict__ in, const __half2* __restrict__ wL1,
                   const float* __restrict__ bias, __half2* __restrict__ out) {
    __shared__ __align__(16) __half2 sm1[L1_WS + L1_PATCH + 264];

    const int tid = threadIdx.x;
    const int wid = tid >> 5, lane = tid & 31;
    const int wm = wid & 1, wn = wid >> 1;
    const int grp = lane >> 2, tg = lane & 3;

    const int b = blockIdx.z;
    const int y0 = blockIdx.x;
    const size_t plane2 = (size_t)258 * 260;
    const __half2* inB = in + (size_t)b * 2 * plane2;
    const uint32_t sm_u32 = (uint32_t)__cvta_generic_to_shared(sm1);

    // zero region init
    for (int i = tid; i < 264; i += 256)
        sm1[L1_WS + L1_PATCH + i] = __floats2half2_rn(0.f, 0.f);

    // prefetch weights (64 oc x 24 half2) and patch (2 pairs x 3 rows x 260)
    for (int id = tid; id < 384; id += 256) {
        int oc = id / 6, q = id - oc * 6;
        cpa16(sm_u32 + (uint32_t)(oc * L1_WST + q * 4) * 4, wL1 + oc * 24 + q * 4);
    }
    for (int rs = wid; rs < 6; rs += 8) {
        int pair = rs / 3, row = rs - pair * 3;
        const __half2* src = inB + (size_t)pair * plane2 + (size_t)(y0 + row) * L1_PW2;
        uint32_t dst = sm_u32 + (uint32_t)(L1_WS + pair * L1_ICS2 + row * L1_PW2) * 4;
        for (int x = lane; x < 65; x += 32)
            cpa16(dst + x * 16, src + x * 4);
    }
    CPA_COMMIT();
    CPA_WAIT0();
    __syncthreads();

    // per-thread B offsets for the 3 k16 groups
    int po[3][2];
#pragma unroll
    for (int q = 0; q < 3; q++)
#pragma unroll
        for (int h = 0; h < 2; h++) {
            int j = q * 8 + tg + h * 4;
            if (j < 18) {
                int tap = j >> 1, p = j & 1;
                po[q][h] = p * L1_ICS2 + (tap / 3) * L1_PW2 + (tap % 3);
            } else {
                po[q][h] = L1_ZOFF;
            }
        }

    int nb[8];
#pragma unroll
    for (int nf = 0; nf < 8; nf++)
        nb[nf] = wn * 64 + nf * 8 + grp;

    float acc[2][8][4];
#pragma unroll
    for (int mf = 0; mf < 2; mf++)
#pragma unroll
        for (int nf = 0; nf < 8; nf++)
#pragma unroll
            for (int k = 0; k < 4; k++) acc[mf][nf][k] = 0.f;

    const uint32_t* Wsu = (const uint32_t*)sm1;
    const uint32_t* patchu = (const uint32_t*)(sm1 + L1_WS);

#pragma unroll
    for (int q = 0; q < 3; q++) {
        uint32_t a[2][4];
#pragma unroll
        for (int mf = 0; mf < 2; mf++) {
            int m = wm * 32 + mf * 16 + grp;
            a[mf][0] = Wsu[m * L1_WST + q * 8 + tg];
            a[mf][1] = Wsu[(m + 8) * L1_WST + q * 8 + tg];
            a[mf][2] = Wsu[m * L1_WST + q * 8 + tg + 4];
            a[mf][3] = Wsu[(m + 8) * L1_WST + q * 8 + tg + 4];
        }
#pragma unroll
        for (int nf = 0; nf < 8; nf++) {
            uint32_t bf[2];
            bf[0] = patchu[po[q][0] + nb[nf]];
            bf[1] = patchu[po[q][1] + nb[nf]];
            MMA_F16(acc[0][nf], a[0], bf);
            MMA_F16(acc[1][nf], a[1], bf);
        }
    }

    __half2* outB = out + (size_t)b * 32 * plane2;
#pragma unroll
    for (int mf = 0; mf < 2; mf++) {
        int oc = wm * 32 + mf * 16 + grp;
        float bv0 = bias[oc], bv1 = bias[oc + 8];
        int P = (wm * 2 + mf) * 8 + grp;
#pragma unroll
        for (int nf = 0; nf < 8; nf++) {
            int col = wn * 64 + nf * 8 + tg * 2;
            __half2* o = outB + (size_t)P * plane2 + (size_t)(y0 + 1) * L1_PW2 + 1 + col;
            o[0] = __floats2half2_rn(fmaxf(acc[mf][nf][0] + bv0, 0.f),
                                     fmaxf(acc[mf][nf][2] + bv1, 0.f));
            o[1] = __floats2half2_rn(fmaxf(acc[mf][nf][1] + bv0, 0.f),
                                     fmaxf(acc[mf][nf][3] + bv1, 0.f));
        }
    }
}

// ---------------------------------------------------------------------------
// fp16 implicit-GEMM 3x3 conv + bias + ReLU, cp.async double-buffered.
// Block 256 thr: 64 oc x 256 px (ROWS x COLS). Warps 2(oc) x 4(px).
// Weights loaded via ldmatrix.x4 (smem stride 76 half2 -> conflict-free rows).
// ---------------------------------------------------------------------------
template <int ROWS, int COLS>
__global__ __launch_bounds__(256, 2)
void conv_mma_f16(const __half2* __restrict__ in, const __half2* __restrict__ wH,
                  const float* __restrict__ bias, __half2* __restrict__ out,
                  int chunks, int OC) {
    constexpr int PW2 = COLS + 4;
    constexpr int PR = ROWS + 2;
    constexpr int ICS2 = (PR * PW2 + 31) / 32 * 32 + 8;
    constexpr int WS_SIZE = 64 * 76;
    constexpr int PATCH_SIZE = 8 * ICS2;
    constexpr int BUF = WS_SIZE + PATCH_SIZE;
    extern __shared__ __half2 sm[];

    const int tid = threadIdx.x;
    const int wid = tid >> 5, lane = tid & 31;
    const int wm = wid & 1, wn = wid >> 1;
    const int grp = lane >> 2, tg = lane & 3;

    const int b = blockIdx.z;
    const int ocg = blockIdx.y;
    const int y0 = blockIdx.x * ROWS;
    const size_t plane2 = (size_t)(COLS + 2) * PW2;

    const __half2* inB = in + (size_t)b * (chunks * 8) * plane2;
    const uint32_t sm_u32 = (uint32_t)__cvta_generic_to_shared(sm);

    const int lr = lane & 7;
    const int lmat = lane >> 3;
    const int lrow = ((lmat & 1) << 3) + lr;
    const int lcol = (lmat >> 1) << 2;

    int nb[8];
#pragma unroll
    for (int nf = 0; nf < 8; nf++) {
        int n = wn * 64 + nf * 8 + grp;
        nb[nf] = (n / COLS) * PW2 + (n % COLS);
    }

    float acc[2][8][4];
#pragma unroll
    for (int mf = 0; mf < 2; mf++)
#pragma unroll
        for (int nf = 0; nf < 8; nf++)
#pragma unroll
            for (int k = 0; k < 4; k++) acc[mf][nf][k] = 0.f;

    auto prefetch = [&](int c, int bi) {
        const __half2* wsrc = wH + ((size_t)c * OC + ocg * 64) * 72;
        uint32_t wdst = sm_u32 + (uint32_t)(bi * BUF) * 4;
        for (int id = tid; id < 1152; id += 256) {
            int oc = id / 18, q = id - oc * 18;
            cpa16(wdst + (oc * 76 + q * 4) * 4, wsrc + oc * 72 + q * 4);
        }
        uint32_t pdst = sm_u32 + (uint32_t)(bi * BUF + WS_SIZE) * 4;
        for (int rs = wid; rs < 8 * PR; rs += 8) {
            int pair = rs / PR, row = rs - pair * PR;
            const __half2* src = inB + (size_t)(c * 8 + pair) * plane2 + (size_t)(y0 + row) * PW2;
            uint32_t dst = pdst + (pair * ICS2 + row * PW2) * 4;
            for (int x = lane; x < PW2 / 4; x += 32)
                cpa16(dst + x * 16, src + x * 4);
        }
    };

    prefetch(0, 0);
    CPA_COMMIT();

    for (int c = 0; c < chunks; c++) {
        const int bi = c & 1;
        if (c > 0) __syncthreads();
        if (c + 1 < chunks) {
            prefetch(c + 1, bi ^ 1);
            CPA_COMMIT();
            CPA_WAIT1();
        } else {
            CPA_WAIT0();
        }
        __syncthreads();

        const uint32_t wsbase = sm_u32 + (uint32_t)(bi * BUF) * 4;
        const uint32_t* patchu = (const uint32_t*)(sm + bi * BUF + WS_SIZE);

#pragma unroll
        for (int tap = 0; tap < 9; tap++) {
            const int toff = (tap / 3) * PW2 + (tap % 3);
            uint32_t a[2][4];
#pragma unroll
            for (int mf = 0; mf < 2; mf++) {
                uint32_t aaddr = wsbase +
                    (uint32_t)(((wm * 32 + mf * 16 + lrow) * 76 + tap * 8 + lcol) * 4);
                LDSM_X4(a[mf][0], a[mf][1], a[mf][2], a[mf][3], aaddr);
            }
#pragma unroll
            for (int nf = 0; nf < 8; nf++) {
                uint32_t bf[2];
                bf[0] = patchu[tg * ICS2 + nb[nf] + toff];
                bf[1] = patchu[(tg + 4) * ICS2 + nb[nf] + toff];
                MMA_F16(acc[0][nf], a[0], bf);
                MMA_F16(acc[1][nf], a[1], bf);
            }
        }
    }

    __half2* outB = out + (size_t)b * (OC / 2) * plane2;
#pragma unroll
    for (int mf = 0; mf < 2; mf++) {
        int oc = ocg * 64 + wm * 32 + mf * 16 + grp;
        float bv0 = bias[oc], bv1 = bias[oc + 8];
        int P = (ocg * 4 + wm * 2 + mf) * 8 + grp;
#pragma unroll
        for (int nf = 0; nf < 8; nf++) {
            int n = wn * 64 + nf * 8 + tg * 2;
            int rp = n / COLS, col = n % COLS;
            __half2* o = outB + (size_t)P * plane2 + (size_t)(y0 + 1 + rp) * PW2 + 1 + col;
            o[0] = __floats2half2_rn(fmaxf(acc[mf][nf][0] + bv0, 0.f),
                                     fmaxf(acc[mf][nf][2] + bv1, 0.f));
            o[1] = __floats2half2_rn(fmaxf(acc[mf][nf][1] + bv0, 0.f),
                                     fmaxf(acc[mf][nf][3] + bv1, 0.f));
        }
    }
}

// ---------------------------------------------------------------------------
// 2x2 maxpool on padded half2 buffers
// ---------------------------------------------------------------------------
__global__ void maxpool_pad_kernel(const __half2* __restrict__ in, __half2* __restrict__ out,
                                   int pairs, int H, int W) {
    int Ho = H / 2, Wo = W / 2;
    long total = (long)BATCH * pairs * Ho * Wo;
    long i = (long)blockIdx.x * blockDim.x + threadIdx.x;
    if (i >= total) return;
    int x = (int)(i % Wo);
    long t = i / Wo;
    int y = (int)(t % Ho); t /= Ho;
    int p = (int)(t % pairs);
    int b = (int)(t / pairs);
    const __half2* s = in + ((size_t)(b * pairs + p) * (H + 2) + (1 + 2 * y)) * (W + 4) + 1 + 2 * x;
    __half2 m = __hmax2(__hmax2(s[0], s[1]), __hmax2(s[W + 4], s[W + 5]));
    out[((size_t)(b * pairs + p) * (Ho + 2) + 1 + y) * (Wo + 4) + 1 + x] = m;
}

// ---------------------------------------------------------------------------
// FUSED transpose + L2-normalize (proven round-15 kernel)
// ---------------------------------------------------------------------------
#define TN_SMEM (32 * 385 * 4 + 128)

__global__ __launch_bounds__(256)
void feat_transnorm_kernel(const __half2* __restrict__ f1, const __half2* __restrict__ f2,
                           const __half2* __restrict__ f3, __half2* __restrict__ out) {
    extern __shared__ __half2 smn[];
    float* sInv = (float*)(smn + 32 * 385);
    const int b = blockIdx.y;
    const int n0 = blockIdx.x * 32;
    const int tx = threadIdx.x, ty = threadIdx.y;
    const int n = n0 + tx, yy = n >> 6, xx = n & 63;
    const size_t base = (size_t)b * 128 * 4488;
    const size_t off = base + (size_t)(1 + yy) * 68 + 1 + xx;

#pragma unroll
    for (int Pg0 = 0; Pg0 < 12; Pg0++) {
        const int Pg = Pg0 * 32;
        const __half2* fb = (Pg < 128) ? f1 : (Pg < 256 ? f2 : f3);
        const int Pl = Pg & 127;
#pragma unroll
        for (int i = 0; i < 4; i++) {
            int c = ty + 8 * i;
            smn[tx * 385 + Pg + c] = fb[off + (size_t)(Pl + c) * 4488];
        }
    }
    __syncthreads();

    {
        int t = ty * 32 + tx;
        int r = t >> 3, j = t & 7;
        float ssq = 0.f;
#pragma unroll
        for (int k = 0; k < 48; k++) {
            float2 v = __half22float2(smn[r * 385 + j + 8 * k]);
            ssq = fmaf(v.x, v.x, fmaf(v.y, v.y, ssq));
        }
        ssq += __shfl_xor_sync(0xffffffff, ssq, 1);
        ssq += __shfl_xor_sync(0xffffffff, ssq, 2);
        ssq += __shfl_xor_sync(0xffffffff, ssq, 4);
        if (j == 0) sInv[r] = 1.0f / (sqrtf(ssq) + 1e-8f);
    }
    __syncthreads();

#pragma unroll
    for (int i = 0; i < 4; i++) {
        int row = ty + 8 * i;
        float inv = sInv[row];
        __half2* orow = out + ((size_t)b * FEATN + n0 + row) * 384;
#pragma unroll
        for (int k = 0; k < 12; k++) {
            float2 v = __half22float2(smn[row * 385 + k * 32 + tx]);
            orow[k * 32 + tx] = __floats2half2_rn(v.x * inv, v.y * inv);
        }
    }
}

__global__ void initmax_kernel(float* __restrict__ g) {
    int i = blockIdx.x * blockDim.x + threadIdx.x;
    if (i < BATCH * FEATN) g[i] = 0.f;
}

// ---------------------------------------------------------------------------
// fp16 mma sim + row-max, cp.async double-buffered, ldmatrix fragment loads.
// ---------------------------------------------------------------------------
#define SIM_TILE 4608

__global__ __launch_bounds__(256, 2)
void simmax_mma_f16(const __half* __restrict__ xT, const __half* __restrict__ sT,
                    float* __restrict__ gmax) {
    extern __shared__ __half2 sm[];

    const int b = blockIdx.z;
    const int nbase = blockIdx.y * 128;
    const int mbase = blockIdx.x * 128;
    const int tid = threadIdx.x;
    const int wid = tid >> 5, lane = tid & 31;
    const int wm = wid & 1, wn = wid >> 1;
    const int grp = lane >> 2, tg = lane & 3;

    const __half2* xb2 = (const __half2*)xT + ((size_t)b * FEATN + nbase) * 384;
    const __half2* sp2 = (const __half2*)sT + ((size_t)b * FEATN + mbase) * 384;
    const uint32_t sm_u32 = (uint32_t)__cvta_generic_to_shared(sm);

    const int lr = lane & 7;
    const int lmat = lane >> 3;
    const int lrowA = ((lmat & 1) << 3) + lr;
    const int lcolA = (lmat >> 1) << 2;
    const int lrowB = lr;
    const int lcolB = (lmat & 1) << 2;

    float acc[4][4][4];
#pragma unroll
    for (int mf = 0; mf < 4; mf++)
#pragma unroll
        for (int nf = 0; nf < 4; nf++)
#pragma unroll
            for (int k = 0; k < 4; k++) acc[mf][nf][k] = 0.f;

    auto prefetch = [&](int chunk, int bi) {
        const int kc2 = chunk * 32;
        uint32_t abase = sm_u32 + (uint32_t)(bi * 2 * SIM_TILE) * 4;
        uint32_t bbase = abase + SIM_TILE * 4;
#pragma unroll
        for (int i = 0; i < 4; i++) {
            int id = tid + i * 256;
            int r = id >> 3, q = (id & 7) * 4;
            cpa16(abase + (r * 36 + q) * 4, xb2 + (size_t)r * 384 + kc2 + q);
            cpa16(bbase + (r * 36 + q) * 4, sp2 + (size_t)r * 384 + kc2 + q);
        }
    };

    prefetch(0, 0);
    CPA_COMMIT();

    for (int chunk = 0; chunk < 12; chunk++) {
        const int bi = chunk & 1;
        if (chunk > 0) __syncthreads();
        if (chunk + 1 < 12) {
            prefetch(chunk + 1, bi ^ 1);
            CPA_COMMIT();
            CPA_WAIT1();
        } else {
            CPA_WAIT0();
        }
        __syncthreads();

        const uint32_t abase = sm_u32 + (uint32_t)(bi * 2 * SIM_TILE) * 4;
        const uint32_t bbase = abase + (uint32_t)SIM_TILE * 4;

#pragma unroll
        for (int ks = 0; ks < 4; ks++) {
            const int kk = ks * 8;
            uint32_t a[4][4];
#pragma unroll
            for (int mf = 0; mf < 4; mf++) {
                uint32_t aaddr = abase +
                    (uint32_t)(((wm * 64 + mf * 16 + lrowA) * 36 + kk + lcolA) * 4);
                LDSM_X4(a[mf][0], a[mf][1], a[mf][2], a[mf][3], aaddr);
            }
#pragma unroll
            for (int nf = 0; nf < 4; nf++) {
                uint32_t bf[2];
                uint32_t baddr = bbase +
                    (uint32_t)(((wn * 32 + nf * 8 + lrowB) * 36 + kk + lcolB) * 4);
                LDSM_X2(bf[0], bf[1], baddr);
                MMA_F16(acc[0][nf], a[0], bf);
                MMA_F16(acc[1][nf], a[1], bf);
                MMA_F16(acc[2][nf], a[2], bf);
                MMA_F16(acc[3][nf], a[3], bf);
            }
        }
    }

#pragma unroll
    for (int mf = 0; mf < 4; mf++) {
        float r0 = 0.f, r1 = 0.f;
#pragma unroll
        for (int nf = 0; nf < 4; nf++) {
            r0 = fmaxf(r0, fmaxf(acc[mf][nf][0], acc[mf][nf][1]));
            r1 = fmaxf(r1, fmaxf(acc[mf][nf][2], acc[mf][nf][3]));
        }
        r0 = fmaxf(r0, __shfl_xor_sync(0xffffffff, r0, 1));
        r0 = fmaxf(r0, __shfl_xor_sync(0xffffffff, r0, 2));
        r1 = fmaxf(r1, __shfl_xor_sync(0xffffffff, r1, 1));
        r1 = fmaxf(r1, __shfl_xor_sync(0xffffffff, r1, 2));
        if (tg == 0) {
            int row = nbase + wm * 64 + mf * 16 + grp;
            atomicMax((int*)&gmax[(size_t)b * FEATN + row], __float_as_int(r0));
            atomicMax((int*)&gmax[(size_t)b * FEATN + row + 8], __float_as_int(r1));
        }
    }
}

// ---------------------------------------------------------------------------
// final reduction
// ---------------------------------------------------------------------------
__global__ void final_loss_kernel(const float* __restrict__ gmax, float* __restrict__ out) {
    __shared__ double sm[256];
    double s = 0.0;
    for (int i = threadIdx.x; i < BATCH * FEATN; i += 256)
        s += 1.0 - (double)gmax[i];
    sm[threadIdx.x] = s;
    __syncthreads();
    for (int st = 128; st > 0; st >>= 1) {
        if (threadIdx.x < st) sm[threadIdx.x] += sm[threadIdx.x + st];
        __syncthreads();
    }
    if (threadIdx.x == 0)
        out[0] = (float)(sm[0] / (double)(BATCH * FEATN));
}

// ---------------------------------------------------------------------------
// host orchestration
// ---------------------------------------------------------------------------
static constexpr int conv_smem(int R, int C) {
    int PW2 = C + 4, PR = R + 2;
    int ICS2 = (PR * PW2 + 31) / 32 * 32 + 8;
    return 2 * (64 * 76 + 8 * ICS2) * 4;
}
#define CS_R1 conv_smem(1, 256)
#define CS_R2 conv_smem(2, 128)
#define CS_R4 conv_smem(4, 64)
#define SIM_SMEM (4 * SIM_TILE * 4)

static void run_stack(const float* img, __half2* wH, const float* const* bs,
                      __half2* pad0, __half2* pad1, __half2* pad2, __half2* pad3,
                      __half2* pad4, __half2* pad5, __half2* pad6,
                      __half2* f1, __half2* f2, __half2* f3, __half* featT) {
    const long o1 = 4608, o2 = 23040, o3 = 59904,
               o4 = 133632, o5 = 281088, o6 = 576000;

    norm_input_pad_kernel<<<(BATCH * 65536 + 255) / 256, 256>>>(img, pad0);

    conv1_mma_f16<<<dim3(256, 1, BATCH), 256>>>(pad0, wH, bs[0], pad1);
    conv_mma_f16<1, 256><<<dim3(256, 1, BATCH), 256, CS_R1>>>(pad1, wH + o1, bs[1], pad2, 4, 64);
    {
        long total = (long)BATCH * 32 * 128 * 128;
        maxpool_pad_kernel<<<(unsigned)((total + 255) / 256), 256>>>(pad2, pad3, 32, 256, 256);
    }
    conv_mma_f16<2, 128><<<dim3(64, 2, BATCH), 256, CS_R2>>>(pad3, wH + o2, bs[2], pad4, 4, 128);
    conv_mma_f16<2, 128><<<dim3(64, 2, BATCH), 256, CS_R2>>>(pad4, wH + o3, bs[3], pad5, 8, 128);
    {
        long total = (long)BATCH * 64 * 64 * 64;
        maxpool_pad_kernel<<<(unsigned)((total + 255) / 256), 256>>>(pad5, pad6, 64, 128, 128);
    }
    conv_mma_f16<4, 64><<<dim3(16, 4, BATCH), 256, CS_R4>>>(pad6, wH + o4, bs[4], f1, 8, 256);
    conv_mma_f16<4, 64><<<dim3(16, 4, BATCH), 256, CS_R4>>>(f1, wH + o5, bs[5], f2, 16, 256);
    conv_mma_f16<4, 64><<<dim3(16, 4, BATCH), 256, CS_R4>>>(f2, wH + o6, bs[6], f3, 16, 256);

    feat_transnorm_kernel<<<dim3(128, BATCH), dim3(32, 8), TN_SMEM>>>(f1, f2, f3, (__half2*)featT);
}

extern "C" void kernel_launch(void* const* d_in, const int* in_sizes, int n_in,
                              void* d_out, int out_size) {
    (void)in_sizes; (void)n_in; (void)out_size;

    __half2 *pad0, *pad1, *pad2, *pad3, *pad4, *pad5, *pad6, *f1, *f2, *f3, *wH;
    __half *xT, *sT;
    float *gmax;
    cudaGetSymbolAddress((void**)&pad0, g_pad0);
    cudaGetSymbolAddress((void**)&pad1, g_pad1);
    cudaGetSymbolAddress((void**)&pad2, g_pad2);
    cudaGetSymbolAddress((void**)&pad3, g_pad3);
    cudaGetSymbolAddress((void**)&pad4, g_pad4);
    cudaGetSymbolAddress((void**)&pad5, g_pad5);
    cudaGetSymbolAddress((void**)&pad6, g_pad6);
    cudaGetSymbolAddress((void**)&f1, g_f1);
    cudaGetSymbolAddress((void**)&f2, g_f2);
    cudaGetSymbolAddress((void**)&f3, g_f3);
    cudaGetSymbolAddress((void**)&xT, g_xT);
    cudaGetSymbolAddress((void**)&sT, g_sT);
    cudaGetSymbolAddress((void**)&wH, g_wH);
    cudaGetSymbolAddress((void**)&gmax, g_maxsim);

    cudaFuncSetAttribute(conv_mma_f16<1, 256>, cudaFuncAttributeMaxDynamicSharedMemorySize, CS_R1);
    cudaFuncSetAttribute(conv_mma_f16<2, 128>, cudaFuncAttributeMaxDynamicSharedMemorySize, CS_R2);
    cudaFuncSetAttribute(conv_mma_f16<4, 64>,  cudaFuncAttributeMaxDynamicSharedMemorySize, CS_R4);
    cudaFuncSetAttribute(simmax_mma_f16, cudaFuncAttributeMaxDynamicSharedMemorySize, SIM_SMEM);
    cudaFuncSetAttribute(feat_transnorm_kernel, cudaFuncAttributeMaxDynamicSharedMemorySize, TN_SMEM);

    const float* outputs = (const float*)d_in[0];
    const float* styles  = (const float*)d_in[1];
    const float* bs[7];
    for (int i = 0; i < 7; i++) bs[i] = (const float*)d_in[3 + 2 * i];

    wtrans_all_kernel<<<(870912 + 255) / 256, 256>>>(
        (const float*)d_in[2], (const float*)d_in[4], (const float*)d_in[6],
        (const float*)d_in[8], (const float*)d_in[10], (const float*)d_in[12],
        (const float*)d_in[14], wH);

    run_stack(outputs, wH, bs, pad0, pad1, pad2, pad3, pad4, pad5, pad6, f1, f2, f3, xT);
    run_stack(styles,  wH, bs, pad0, pad1, pad2, pad3, pad4, pad5, pad6, f1, f2, f3, sT);

    initmax_kernel<<<(BATCH * FEATN + 255) / 256, 256>>>(gmax);
    simmax_mma_f16<<<dim3(FEATN / 128, FEATN / 128, BATCH), 256, SIM_SMEM>>>(xT, sT, gmax);
    final_loss_kernel<<<1, 256>>>(gmax, (float*)d_out);
}

// round 17
// speedup vs baseline: 1.5375x; 1.5375x over previous
#include <cuda_runtime.h>
#include <cuda_fp16.h>
#include <cstdint>
#include <math.h>

// ---------------------------------------------------------------------------
// VGG16-block3 features on outputs+styles [4,3,256,256], then
// loss = mean_{b,n} (1 - max_m xn[b,n].sn[b,m]),  C=768, N=M=4096.
//
// Full fp16 datapath (fp32 accumulate) on m16n8k16 MMA, cp.async-pipelined,
// fragment loads via ldmatrix (LDSM). Round-16 configuration, re-measured:
// specialized tap-packed layer-1 conv (K=36: 3 MMAs vs 9), fused wtrans,
// fused transpose+rownorm. Activations: zero-padded channel-pair half2
// layout [C/2][H+2][W+4]; storage pair P=(chunk c, p) holds logical channels
// (16c+p, 16c+8+p). Weights permuted to match. Padded borders rely on .bss
// zero-init, never written.
// ---------------------------------------------------------------------------

#define BATCH 4
#define FEATC 768
#define FEATN 4096

__device__ __half2 g_pad0[(size_t)BATCH * 2 * 258 * 260];   // layer-1 input: 2 pairs
__device__ __half2 g_pad1[(size_t)BATCH * 32 * 258 * 260];
__device__ __half2 g_pad2[(size_t)BATCH * 32 * 258 * 260];
__device__ __half2 g_pad3[(size_t)BATCH * 32 * 130 * 132];
__device__ __half2 g_pad4[(size_t)BATCH * 64 * 130 * 132];
__device__ __half2 g_pad5[(size_t)BATCH * 64 * 130 * 132];
__device__ __half2 g_pad6[(size_t)BATCH * 64 * 66 * 68];
__device__ __half2 g_f1[(size_t)BATCH * 128 * 66 * 68];
__device__ __half2 g_f2[(size_t)BATCH * 128 * 66 * 68];
__device__ __half2 g_f3[(size_t)BATCH * 128 * 66 * 68];
__device__ __half  g_xT[(size_t)BATCH * FEATN * FEATC];
__device__ __half  g_sT[(size_t)BATCH * FEATN * FEATC];
__device__ __half2 g_wH[870912];
__device__ float   g_maxsim[BATCH * FEATN];

#define MMA_F16(c, a, bfr) \
    asm volatile("mma.sync.aligned.m16n8k16.row.col.f32.f16.f16.f32 " \
        "{%0,%1,%2,%3}, {%4,%5,%6,%7}, {%8,%9}, {%0,%1,%2,%3};" \
        : "+f"((c)[0]), "+f"((c)[1]), "+f"((c)[2]), "+f"((c)[3]) \
        : "r"((a)[0]), "r"((a)[1]), "r"((a)[2]), "r"((a)[3]), \
          "r"((bfr)[0]), "r"((bfr)[1]))

#define LDSM_X4(r0, r1, r2, r3, addr) \
    asm volatile("ldmatrix.sync.aligned.m8n8.x4.shared.b16 {%0,%1,%2,%3}, [%4];" \
        : "=r"(r0), "=r"(r1), "=r"(r2), "=r"(r3) : "r"(addr))
#define LDSM_X2(r0, r1, addr) \
    asm volatile("ldmatrix.sync.aligned.m8n8.x2.shared.b16 {%0,%1}, [%2];" \
        : "=r"(r0), "=r"(r1) : "r"(addr))

__device__ __forceinline__ void cpa16(uint32_t dst, const void* src) {
    asm volatile("cp.async.cg.shared.global [%0], [%1], 16;" :: "r"(dst), "l"(src));
}
#define CPA_COMMIT() asm volatile("cp.async.commit_group;" ::: "memory")
#define CPA_WAIT1()  asm volatile("cp.async.wait_group 1;" ::: "memory")
#define CPA_WAIT0()  asm volatile("cp.async.wait_group 0;" ::: "memory")

// ---------------------------------------------------------------------------
// input normalization -> layer-1 pair layout: pair0=(ch0,ch1), pair1=(ch2,0)
// ---------------------------------------------------------------------------
__global__ void norm_input_pad_kernel(const float* __restrict__ in, __half2* __restrict__ out) {
    int i = blockIdx.x * blockDim.x + threadIdx.x;
    if (i >= BATCH * 65536) return;
    int x = i & 255, y = (i >> 8) & 255;
    int b = i >> 16;
    const float mean[3] = {0.485f, 0.456f, 0.406f};
    const float stdv[3] = {0.229f, 0.224f, 0.225f};
    const float* src = in + ((size_t)b * 3 << 16) + (y << 8) + x;
    float v0 = (src[0] - mean[0]) / stdv[0];
    float v1 = (src[65536] - mean[1]) / stdv[1];
    float v2 = (src[131072] - mean[2]) / stdv[2];
    size_t o = ((size_t)(b * 2) * 258 + 1 + y) * 260 + 1 + x;
    out[o] = __floats2half2_rn(v0, v1);
    out[o + (size_t)258 * 260] = __floats2half2_rn(v2, 0.f);
}

// ---------------------------------------------------------------------------
// fused weight transform (single launch):
// segment 0 (i<1536): layer-1 tap-packed wL1[oc][24]: j=tap*2+p ->
//   half2 = (w0[oc][2p][tap], w0[oc][2p+1][tap]), zero for j>=18 / ch>=3.
// segments 1..6: generic wH[seg + (c*OC+oc)*72 + t*8 + p].
// ---------------------------------------------------------------------------
__global__ void wtrans_all_kernel(const float* __restrict__ w0, const float* __restrict__ w1,
                                  const float* __restrict__ w2, const float* __restrict__ w3,
                                  const float* __restrict__ w4, const float* __restrict__ w5,
                                  const float* __restrict__ w6, __half2* __restrict__ wH) {
    const int i = blockIdx.x * blockDim.x + threadIdx.x;
    if (i >= 870912) return;
    if (i < 4608) {
        float v0 = 0.f, v1 = 0.f;
        if (i < 1536) {
            int oc = i / 24, j = i % 24;
            if (j < 18) {
                int tap = j >> 1, p = j & 1;
                v0 = w0[oc * 27 + (2 * p) * 9 + tap];
                if (2 * p + 1 < 3) v1 = w0[oc * 27 + (2 * p + 1) * 9 + tap];
            }
        }
        wH[i] = __floats2half2_rn(v0, v1);
        return;
    }
    const int ends[7] = {4608, 23040, 59904, 133632, 281088, 576000, 870912};
    const int OCt[7] = {64, 64, 128, 128, 256, 256, 256};
    const int Cint[7] = {3, 64, 64, 128, 128, 256, 256};
    int L = 1;
    while (i >= ends[L]) L++;
    int base = ends[L - 1];
    const float* wsrc[7] = {w0, w1, w2, w3, w4, w5, w6};
    const float* w = wsrc[L];
    int OC = OCt[L], Cin = Cint[L];
    int j = i - base;
    int within = j % 72;
    int t = within >> 3, p = within & 7;
    int oc = (j / 72) % OC;
    int c = j / (72 * OC);
    int ic0 = 16 * c + p, ic1 = ic0 + 8;
    float v0 = (ic0 < Cin) ? w[((size_t)oc * Cin + ic0) * 9 + t] : 0.f;
    float v1 = (ic1 < Cin) ? w[((size_t)oc * Cin + ic1) * 9 + t] : 0.f;
    wH[i] = __floats2half2_rn(v0, v1);
}

// ---------------------------------------------------------------------------
// specialized layer-1 conv: 3->64, tap-packed K=36 (18 pairs), 3 MMAs.
// Block 256 thr: 64 oc x 256 px (1 row). Warps 2(oc) x 4(px).
// ---------------------------------------------------------------------------
#define L1_PW2 260
#define L1_ICS2 808
#define L1_WST 28
#define L1_WS (64 * L1_WST)
#define L1_PATCH (2 * L1_ICS2)
#define L1_ZOFF L1_PATCH

__global__ __launch_bounds__(256, 2)
void conv1_mma_f16(const __half2* __restrict__ in, const __half2* __restrict__ wL1,
                   const float* __restrict__ bias, __half2* __restrict__ out) {
    __shared__ __align__(16) __half2 sm1[L1_WS + L1_PATCH + 264];

    const int tid = threadIdx.x;
    const int wid = tid >> 5, lane = tid & 31;
    const int wm = wid & 1, wn = wid >> 1;
    const int grp = lane >> 2, tg = lane & 3;

    const int b = blockIdx.z;
    const int y0 = blockIdx.x;
    const size_t plane2 = (size_t)258 * 260;
    const __half2* inB = in + (size_t)b * 2 * plane2;
    const uint32_t sm_u32 = (uint32_t)__cvta_generic_to_shared(sm1);

    for (int i = tid; i < 264; i += 256)
        sm1[L1_WS + L1_PATCH + i] = __floats2half2_rn(0.f, 0.f);

    for (int id = tid; id < 384; id += 256) {
        int oc = id / 6, q = id - oc * 6;
        cpa16(sm_u32 + (uint32_t)(oc * L1_WST + q * 4) * 4, wL1 + oc * 24 + q * 4);
    }
    for (int rs = wid; rs < 6; rs += 8) {
        int pair = rs / 3, row = rs - pair * 3;
        const __half2* src = inB + (size_t)pair * plane2 + (size_t)(y0 + row) * L1_PW2;
        uint32_t dst = sm_u32 + (uint32_t)(L1_WS + pair * L1_ICS2 + row * L1_PW2) * 4;
        for (int x = lane; x < 65; x += 32)
            cpa16(dst + x * 16, src + x * 4);
    }
    CPA_COMMIT();
    CPA_WAIT0();
    __syncthreads();

    int po[3][2];
#pragma unroll
    for (int q = 0; q < 3; q++)
#pragma unroll
        for (int h = 0; h < 2; h++) {
            int j = q * 8 + tg + h * 4;
            if (j < 18) {
                int tap = j >> 1, p = j & 1;
                po[q][h] = p * L1_ICS2 + (tap / 3) * L1_PW2 + (tap % 3);
            } else {
                po[q][h] = L1_ZOFF;
            }
        }

    int nb[8];
#pragma unroll
    for (int nf = 0; nf < 8; nf++)
        nb[nf] = wn * 64 + nf * 8 + grp;

    float acc[2][8][4];
#pragma unroll
    for (int mf = 0; mf < 2; mf++)
#pragma unroll
        for (int nf = 0; nf < 8; nf++)
#pragma unroll
            for (int k = 0; k < 4; k++) acc[mf][nf][k] = 0.f;

    const uint32_t* Wsu = (const uint32_t*)sm1;
    const uint32_t* patchu = (const uint32_t*)(sm1 + L1_WS);

#pragma unroll
    for (int q = 0; q < 3; q++) {
        uint32_t a[2][4];
#pragma unroll
        for (int mf = 0; mf < 2; mf++) {
            int m = wm * 32 + mf * 16 + grp;
            a[mf][0] = Wsu[m * L1_WST + q * 8 + tg];
            a[mf][1] = Wsu[(m + 8) * L1_WST + q * 8 + tg];
            a[mf][2] = Wsu[m * L1_WST + q * 8 + tg + 4];
            a[mf][3] = Wsu[(m + 8) * L1_WST + q * 8 + tg + 4];
        }
#pragma unroll
        for (int nf = 0; nf < 8; nf++) {
            uint32_t bf[2];
            bf[0] = patchu[po[q][0] + nb[nf]];
            bf[1] = patchu[po[q][1] + nb[nf]];
            MMA_F16(acc[0][nf], a[0], bf);
            MMA_F16(acc[1][nf], a[1], bf);
        }
    }

    __half2* outB = out + (size_t)b * 32 * plane2;
#pragma unroll
    for (int mf = 0; mf < 2; mf++) {
        int oc = wm * 32 + mf * 16 + grp;
        float bv0 = bias[oc], bv1 = bias[oc + 8];
        int P = (wm * 2 + mf) * 8 + grp;
#pragma unroll
        for (int nf = 0; nf < 8; nf++) {
            int col = wn * 64 + nf * 8 + tg * 2;
            __half2* o = outB + (size_t)P * plane2 + (size_t)(y0 + 1) * L1_PW2 + 1 + col;
            o[0] = __floats2half2_rn(fmaxf(acc[mf][nf][0] + bv0, 0.f),
                                     fmaxf(acc[mf][nf][2] + bv1, 0.f));
            o[1] = __floats2half2_rn(fmaxf(acc[mf][nf][1] + bv0, 0.f),
                                     fmaxf(acc[mf][nf][3] + bv1, 0.f));
        }
    }
}

// ---------------------------------------------------------------------------
// fp16 implicit-GEMM 3x3 conv + bias + ReLU, cp.async double-buffered.
// ---------------------------------------------------------------------------
template <int ROWS, int COLS>
__global__ __launch_bounds__(256, 2)
void conv_mma_f16(const __half2* __restrict__ in, const __half2* __restrict__ wH,
                  const float* __restrict__ bias, __half2* __restrict__ out,
                  int chunks, int OC) {
    constexpr int PW2 = COLS + 4;
    constexpr int PR = ROWS + 2;
    constexpr int ICS2 = (PR * PW2 + 31) / 32 * 32 + 8;
    constexpr int WS_SIZE = 64 * 76;
    constexpr int PATCH_SIZE = 8 * ICS2;
    constexpr int BUF = WS_SIZE + PATCH_SIZE;
    extern __shared__ __half2 sm[];

    const int tid = threadIdx.x;
    const int wid = tid >> 5, lane = tid & 31;
    const int wm = wid & 1, wn = wid >> 1;
    const int grp = lane >> 2, tg = lane & 3;

    const int b = blockIdx.z;
    const int ocg = blockIdx.y;
    const int y0 = blockIdx.x * ROWS;
    const size_t plane2 = (size_t)(COLS + 2) * PW2;

    const __half2* inB = in + (size_t)b * (chunks * 8) * plane2;
    const uint32_t sm_u32 = (uint32_t)__cvta_generic_to_shared(sm);

    const int lr = lane & 7;
    const int lmat = lane >> 3;
    const int lrow = ((lmat & 1) << 3) + lr;
    const int lcol = (lmat >> 1) << 2;

    int nb[8];
#pragma unroll
    for (int nf = 0; nf < 8; nf++) {
        int n = wn * 64 + nf * 8 + grp;
        nb[nf] = (n / COLS) * PW2 + (n % COLS);
    }

    float acc[2][8][4];
#pragma unroll
    for (int mf = 0; mf < 2; mf++)
#pragma unroll
        for (int nf = 0; nf < 8; nf++)
#pragma unroll
            for (int k = 0; k < 4; k++) acc[mf][nf][k] = 0.f;

    auto prefetch = [&](int c, int bi) {
        const __half2* wsrc = wH + ((size_t)c * OC + ocg * 64) * 72;
        uint32_t wdst = sm_u32 + (uint32_t)(bi * BUF) * 4;
        for (int id = tid; id < 1152; id += 256) {
            int oc = id / 18, q = id - oc * 18;
            cpa16(wdst + (oc * 76 + q * 4) * 4, wsrc + oc * 72 + q * 4);
        }
        uint32_t pdst = sm_u32 + (uint32_t)(bi * BUF + WS_SIZE) * 4;
        for (int rs = wid; rs < 8 * PR; rs += 8) {
            int pair = rs / PR, row = rs - pair * PR;
            const __half2* src = inB + (size_t)(c * 8 + pair) * plane2 + (size_t)(y0 + row) * PW2;
            uint32_t dst = pdst + (pair * ICS2 + row * PW2) * 4;
            for (int x = lane; x < PW2 / 4; x += 32)
                cpa16(dst + x * 16, src + x * 4);
        }
    };

    prefetch(0, 0);
    CPA_COMMIT();

    for (int c = 0; c < chunks; c++) {
        const int bi = c & 1;
        if (c > 0) __syncthreads();
        if (c + 1 < chunks) {
            prefetch(c + 1, bi ^ 1);
            CPA_COMMIT();
            CPA_WAIT1();
        } else {
            CPA_WAIT0();
        }
        __syncthreads();

        const uint32_t wsbase = sm_u32 + (uint32_t)(bi * BUF) * 4;
        const uint32_t* patchu = (const uint32_t*)(sm + bi * BUF + WS_SIZE);

#pragma unroll
        for (int tap = 0; tap < 9; tap++) {
            const int toff = (tap / 3) * PW2 + (tap % 3);
            uint32_t a[2][4];
#pragma unroll
            for (int mf = 0; mf < 2; mf++) {
                uint32_t aaddr = wsbase +
                    (uint32_t)(((wm * 32 + mf * 16 + lrow) * 76 + tap * 8 + lcol) * 4);
                LDSM_X4(a[mf][0], a[mf][1], a[mf][2], a[mf][3], aaddr);
            }
#pragma unroll
            for (int nf = 0; nf < 8; nf++) {
                uint32_t bf[2];
                bf[0] = patchu[tg * ICS2 + nb[nf] + toff];
                bf[1] = patchu[(tg + 4) * ICS2 + nb[nf] + toff];
                MMA_F16(acc[0][nf], a[0], bf);
                MMA_F16(acc[1][nf], a[1], bf);
            }
        }
    }

    __half2* outB = out + (size_t)b * (OC / 2) * plane2;
#pragma unroll
    for (int mf = 0; mf < 2; mf++) {
        int oc = ocg * 64 + wm * 32 + mf * 16 + grp;
        float bv0 = bias[oc], bv1 = bias[oc + 8];
        int P = (ocg * 4 + wm * 2 + mf) * 8 + grp;
#pragma unroll
        for (int nf = 0; nf < 8; nf++) {
            int n = wn * 64 + nf * 8 + tg * 2;
            int rp = n / COLS, col = n % COLS;
            __half2* o = outB + (size_t)P * plane2 + (size_t)(y0 + 1 + rp) * PW2 + 1 + col;
            o[0] = __floats2half2_rn(fmaxf(acc[mf][nf][0] + bv0, 0.f),
                                     fmaxf(acc[mf][nf][2] + bv1, 0.f));
            o[1] = __floats2half2_rn(fmaxf(acc[mf][nf][1] + bv0, 0.f),
                                     fmaxf(acc[mf][nf][3] + bv1, 0.f));
        }
    }
}

// ---------------------------------------------------------------------------
// 2x2 maxpool on padded half2 buffers
// ---------------------------------------------------------------------------
__global__ void maxpool_pad_kernel(const __half2* __restrict__ in, __half2* __restrict__ out,
                                   int pairs, int H, int W) {
    int Ho = H / 2, Wo = W / 2;
    long total = (long)BATCH * pairs * Ho * Wo;
    long i = (long)blockIdx.x * blockDim.x + threadIdx.x;
    if (i >= total) return;
    int x = (int)(i % Wo);
    long t = i / Wo;
    int y = (int)(t % Ho); t /= Ho;
    int p = (int)(t % pairs);
    int b = (int)(t / pairs);
    const __half2* s = in + ((size_t)(b * pairs + p) * (H + 2) + (1 + 2 * y)) * (W + 4) + 1 + 2 * x;
    __half2 m = __hmax2(__hmax2(s[0], s[1]), __hmax2(s[W + 4], s[W + 5]));
    out[((size_t)(b * pairs + p) * (Ho + 2) + 1 + y) * (Wo + 4) + 1 + x] = m;
}

// ---------------------------------------------------------------------------
// FUSED transpose + L2-normalize
// ---------------------------------------------------------------------------
#define TN_SMEM (32 * 385 * 4 + 128)

__global__ __launch_bounds__(256)
void feat_transnorm_kernel(const __half2* __restrict__ f1, const __half2* __restrict__ f2,
                           const __half2* __restrict__ f3, __half2* __restrict__ out) {
    extern __shared__ __half2 smn[];
    float* sInv = (float*)(smn + 32 * 385);
    const int b = blockIdx.y;
    const int n0 = blockIdx.x * 32;
    const int tx = threadIdx.x, ty = threadIdx.y;
    const int n = n0 + tx, yy = n >> 6, xx = n & 63;
    const size_t base = (size_t)b * 128 * 4488;
    const size_t off = base + (size_t)(1 + yy) * 68 + 1 + xx;

#pragma unroll
    for (int Pg0 = 0; Pg0 < 12; Pg0++) {
        const int Pg = Pg0 * 32;
        const __half2* fb = (Pg < 128) ? f1 : (Pg < 256 ? f2 : f3);
        const int Pl = Pg & 127;
#pragma unroll
        for (int i = 0; i < 4; i++) {
            int c = ty + 8 * i;
            smn[tx * 385 + Pg + c] = fb[off + (size_t)(Pl + c) * 4488];
        }
    }
    __syncthreads();

    {
        int t = ty * 32 + tx;
        int r = t >> 3, j = t & 7;
        float ssq = 0.f;
#pragma unroll
        for (int k = 0; k < 48; k++) {
            float2 v = __half22float2(smn[r * 385 + j + 8 * k]);
            ssq = fmaf(v.x, v.x, fmaf(v.y, v.y, ssq));
        }
        ssq += __shfl_xor_sync(0xffffffff, ssq, 1);
        ssq += __shfl_xor_sync(0xffffffff, ssq, 2);
        ssq += __shfl_xor_sync(0xffffffff, ssq, 4);
        if (j == 0) sInv[r] = 1.0f / (sqrtf(ssq) + 1e-8f);
    }
    __syncthreads();

#pragma unroll
    for (int i = 0; i < 4; i++) {
        int row = ty + 8 * i;
        float inv = sInv[row];
        __half2* orow = out + ((size_t)b * FEATN + n0 + row) * 384;
#pragma unroll
        for (int k = 0; k < 12; k++) {
            float2 v = __half22float2(smn[row * 385 + k * 32 + tx]);
            orow[k * 32 + tx] = __floats2half2_rn(v.x * inv, v.y * inv);
        }
    }
}

__global__ void initmax_kernel(float* __restrict__ g) {
    int i = blockIdx.x * blockDim.x + threadIdx.x;
    if (i < BATCH * FEATN) g[i] = 0.f;
}

// ---------------------------------------------------------------------------
// fp16 mma sim + row-max, cp.async double-buffered, ldmatrix fragment loads.
// ---------------------------------------------------------------------------
#define SIM_TILE 4608

__global__ __launch_bounds__(256, 2)
void simmax_mma_f16(const __half* __restrict__ xT, const __half* __restrict__ sT,
                    float* __restrict__ gmax) {
    extern __shared__ __half2 sm[];

    const int b = blockIdx.z;
    const int nbase = blockIdx.y * 128;
    const int mbase = blockIdx.x * 128;
    const int tid = threadIdx.x;
    const int wid = tid >> 5, lane = tid & 31;
    const int wm = wid & 1, wn = wid >> 1;
    const int grp = lane >> 2, tg = lane & 3;

    const __half2* xb2 = (const __half2*)xT + ((size_t)b * FEATN + nbase) * 384;
    const __half2* sp2 = (const __half2*)sT + ((size_t)b * FEATN + mbase) * 384;
    const uint32_t sm_u32 = (uint32_t)__cvta_generic_to_shared(sm);

    const int lr = lane & 7;
    const int lmat = lane >> 3;
    const int lrowA = ((lmat & 1) << 3) + lr;
    const int lcolA = (lmat >> 1) << 2;
    const int lrowB = lr;
    const int lcolB = (lmat & 1) << 2;

    float acc[4][4][4];
#pragma unroll
    for (int mf = 0; mf < 4; mf++)
#pragma unroll
        for (int nf = 0; nf < 4; nf++)
#pragma unroll
            for (int k = 0; k < 4; k++) acc[mf][nf][k] = 0.f;

    auto prefetch = [&](int chunk, int bi) {
        const int kc2 = chunk * 32;
        uint32_t abase = sm_u32 + (uint32_t)(bi * 2 * SIM_TILE) * 4;
        uint32_t bbase = abase + SIM_TILE * 4;
#pragma unroll
        for (int i = 0; i < 4; i++) {
            int id = tid + i * 256;
            int r = id >> 3, q = (id & 7) * 4;
            cpa16(abase + (r * 36 + q) * 4, xb2 + (size_t)r * 384 + kc2 + q);
            cpa16(bbase + (r * 36 + q) * 4, sp2 + (size_t)r * 384 + kc2 + q);
        }
    };

    prefetch(0, 0);
    CPA_COMMIT();

    for (int chunk = 0; chunk < 12; chunk++) {
        const int bi = chunk & 1;
        if (chunk > 0) __syncthreads();
        if (chunk + 1 < 12) {
            prefetch(chunk + 1, bi ^ 1);
            CPA_COMMIT();
            CPA_WAIT1();
        } else {
            CPA_WAIT0();
        }
        __syncthreads();

        const uint32_t abase = sm_u32 + (uint32_t)(bi * 2 * SIM_TILE) * 4;
        const uint32_t bbase = abase + (uint32_t)SIM_TILE * 4;

#pragma unroll
        for (int ks = 0; ks < 4; ks++) {
            const int kk = ks * 8;
            uint32_t a[4][4];
#pragma unroll
            for (int mf = 0; mf < 4; mf++) {
                uint32_t aaddr = abase +
                    (uint32_t)(((wm * 64 + mf * 16 + lrowA) * 36 + kk + lcolA) * 4);
                LDSM_X4(a[mf][0], a[mf][1], a[mf][2], a[mf][3], aaddr);
            }
#pragma unroll
            for (int nf = 0; nf < 4; nf++) {
                uint32_t bf[2];
                uint32_t baddr = bbase +
                    (uint32_t)(((wn * 32 + nf * 8 + lrowB) * 36 + kk + lcolB) * 4);
                LDSM_X2(bf[0], bf[1], baddr);
                MMA_F16(acc[0][nf], a[0], bf);
                MMA_F16(acc[1][nf], a[1], bf);
                MMA_F16(acc[2][nf], a[2], bf);
                MMA_F16(acc[3][nf], a[3], bf);
            }
        }
    }

#pragma unroll
    for (int mf = 0; mf < 4; mf++) {
        float r0 = 0.f, r1 = 0.f;
#pragma unroll
        for (int nf = 0; nf < 4; nf++) {
            r0 = fmaxf(r0, fmaxf(acc[mf][nf][0], acc[mf][nf][1]));
            r1 = fmaxf(r1, fmaxf(acc[mf][nf][2], acc[mf][nf][3]));
        }
        r0 = fmaxf(r0, __shfl_xor_sync(0xffffffff, r0, 1));
        r0 = fmaxf(r0, __shfl_xor_sync(0xffffffff, r0, 2));
        r1 = fmaxf(r1, __shfl_xor_sync(0xffffffff, r1, 1));
        r1 = fmaxf(r1, __shfl_xor_sync(0xffffffff, r1, 2));
        if (tg == 0) {
            int row = nbase + wm * 64 + mf * 16 + grp;
            atomicMax((int*)&gmax[(size_t)b * FEATN + row], __float_as_int(r0));
            atomicMax((int*)&gmax[(size_t)b * FEATN + row + 8], __float_as_int(r1));
        }
    }
}

// ---------------------------------------------------------------------------
// final reduction
// ---------------------------------------------------------------------------
__global__ void final_loss_kernel(const float* __restrict__ gmax, float* __restrict__ out) {
    __shared__ double sm[256];
    double s = 0.0;
    for (int i = threadIdx.x; i < BATCH * FEATN; i += 256)
        s += 1.0 - (double)gmax[i];
    sm[threadIdx.x] = s;
    __syncthreads();
    for (int st = 128; st > 0; st >>= 1) {
        if (threadIdx.x < st) sm[threadIdx.x] += sm[threadIdx.x + st];
        __syncthreads();
    }
    if (threadIdx.x == 0)
        out[0] = (float)(sm[0] / (double)(BATCH * FEATN));
}

// ---------------------------------------------------------------------------
// host orchestration
// ---------------------------------------------------------------------------
static constexpr int conv_smem(int R, int C) {
    int PW2 = C + 4, PR = R + 2;
    int ICS2 = (PR * PW2 + 31) / 32 * 32 + 8;
    return 2 * (64 * 76 + 8 * ICS2) * 4;
}
#define CS_R1 conv_smem(1, 256)
#define CS_R2 conv_smem(2, 128)
#define CS_R4 conv_smem(4, 64)
#define SIM_SMEM (4 * SIM_TILE * 4)

static void run_stack(const float* img, __half2* wH, const float* const* bs,
                      __half2* pad0, __half2* pad1, __half2* pad2, __half2* pad3,
                      __half2* pad4, __half2* pad5, __half2* pad6,
                      __half2* f1, __half2* f2, __half2* f3, __half* featT) {
    const long o1 = 4608, o2 = 23040, o3 = 59904,
               o4 = 133632, o5 = 281088, o6 = 576000;

    norm_input_pad_kernel<<<(BATCH * 65536 + 255) / 256, 256>>>(img, pad0);

    conv1_mma_f16<<<dim3(256, 1, BATCH), 256>>>(pad0, wH, bs[0], pad1);
    conv_mma_f16<1, 256><<<dim3(256, 1, BATCH), 256, CS_R1>>>(pad1, wH + o1, bs[1], pad2, 4, 64);
    {
        long total = (long)BATCH * 32 * 128 * 128;
        maxpool_pad_kernel<<<(unsigned)((total + 255) / 256), 256>>>(pad2, pad3, 32, 256, 256);
    }
    conv_mma_f16<2, 128><<<dim3(64, 2, BATCH), 256, CS_R2>>>(pad3, wH + o2, bs[2], pad4, 4, 128);
    conv_mma_f16<2, 128><<<dim3(64, 2, BATCH), 256, CS_R2>>>(pad4, wH + o3, bs[3], pad5, 8, 128);
    {
        long total = (long)BATCH * 64 * 64 * 64;
        maxpool_pad_kernel<<<(unsigned)((total + 255) / 256), 256>>>(pad5, pad6, 64, 128, 128);
    }
    conv_mma_f16<4, 64><<<dim3(16, 4, BATCH), 256, CS_R4>>>(pad6, wH + o4, bs[4], f1, 8, 256);
    conv_mma_f16<4, 64><<<dim3(16, 4, BATCH), 256, CS_R4>>>(f1, wH + o5, bs[5], f2, 16, 256);
    conv_mma_f16<4, 64><<<dim3(16, 4, BATCH), 256, CS_R4>>>(f2, wH + o6, bs[6], f3, 16, 256);

    feat_transnorm_kernel<<<dim3(128, BATCH), dim3(32, 8), TN_SMEM>>>(f1, f2, f3, (__half2*)featT);
}

extern "C" void kernel_launch(void* const* d_in, const int* in_sizes, int n_in,
                              void* d_out, int out_size) {
    (void)in_sizes; (void)n_in; (void)out_size;

    __half2 *pad0, *pad1, *pad2, *pad3, *pad4, *pad5, *pad6, *f1, *f2, *f3, *wH;
    __half *xT, *sT;
    float *gmax;
    cudaGetSymbolAddress((void**)&pad0, g_pad0);
    cudaGetSymbolAddress((void**)&pad1, g_pad1);
    cudaGetSymbolAddress((void**)&pad2, g_pad2);
    cudaGetSymbolAddress((void**)&pad3, g_pad3);
    cudaGetSymbolAddress((void**)&pad4, g_pad4);
    cudaGetSymbolAddress((void**)&pad5, g_pad5);
    cudaGetSymbolAddress((void**)&pad6, g_pad6);
    cudaGetSymbolAddress((void**)&f1, g_f1);
    cudaGetSymbolAddress((void**)&f2, g_f2);
    cudaGetSymbolAddress((void**)&f3, g_f3);
    cudaGetSymbolAddress((void**)&xT, g_xT);
    cudaGetSymbolAddress((void**)&sT, g_sT);
    cudaGetSymbolAddress((void**)&wH, g_wH);
    cudaGetSymbolAddress((void**)&gmax, g_maxsim);

    cudaFuncSetAttribute(conv_mma_f16<1, 256>, cudaFuncAttributeMaxDynamicSharedMemorySize, CS_R1);
    cudaFuncSetAttribute(conv_mma_f16<2, 128>, cudaFuncAttributeMaxDynamicSharedMemorySize, CS_R2);
    cudaFuncSetAttribute(conv_mma_f16<4, 64>,  cudaFuncAttributeMaxDynamicSharedMemorySize, CS_R4);
    cudaFuncSetAttribute(simmax_mma_f16, cudaFuncAttributeMaxDynamicSharedMemorySize, SIM_SMEM);
    cudaFuncSetAttribute(feat_transnorm_kernel, cudaFuncAttributeMaxDynamicSharedMemorySize, TN_SMEM);

    const float* outputs = (const float*)d_in[0];
    const float* styles  = (const float*)d_in[1];
    const float* bs[7];
    for (int i = 0; i < 7; i++) bs[i] = (const float*)d_in[3 + 2 * i];

    wtrans_all_kernel<<<(870912 + 255) / 256, 256>>>(
        (const float*)d_in[2], (const float*)d_in[4], (const float*)d_in[6],
        (const float*)d_in[8], (const float*)d_in[10], (const float*)d_in[12],
        (const float*)d_in[14], wH);

    run_stack(outputs, wH, bs, pad0, pad1, pad2, pad3, pad4, pad5, pad6, f1, f2, f3, xT);
    run_stack(styles,  wH, bs, pad0, pad1, pad2, pad3, pad4, pad5, pad6, f1, f2, f3, sT);

    initmax_kernel<<<(BATCH * FEATN + 255) / 256, 256>>>(gmax);
    simmax_mma_f16<<<dim3(FEATN / 128, FEATN / 128, BATCH), 256, SIM_SMEM>>>(xT, sT, gmax);
    final_loss_kernel<<<1, 256>>>(gmax, (float*)d_out);
}